// round 13
// baseline (speedup 1.0000x reference)
#include <cuda_runtime.h>
#include <cstdint>
#include <math.h>

#define BS   256
#define NJ   55
#define NV   10475
#define NN   (NV*3)      // 31425
#define KSH  60
#define KTOT 546
#define KPAD 576
#define PITCH 133
#define NCH  64
#define VT   164

__constant__ int c_parents[NJ] = {-1,0,0,0,1,2,3,4,5,6,7,8,9,9,9,12,13,14,16,17,18,19,
                                  15,15,15,20,25,26,20,28,29,20,31,32,20,34,35,20,37,38,
                                  21,40,41,21,43,44,21,46,47,21,49,50,21,52,53};

// ---- scratch ----
__device__ float g_F[BS*KPAD];             // feature matrix row-major [b][k], zero-padded
__device__ float g_rot[BS*NJ*9];
__device__ float g_JSDp[NCH*NJ*184];
__device__ float g_JSD[NJ*180];
__device__ float g_Jvt[NJ*3];
__device__ float g_joints[BS*NJ*3];
__device__ float g_Arel[BS*NJ*12];
__device__ float g_SDT[(size_t)KSH*NN];    // 7.5 MB, compacted shapedirs [k][n]
__device__ float g_vposed[BS*NN];          // 32.2 MB

// ============================================================================
// tf32 warp MMA helpers (standard PTX, compiles for plain sm_103)
// ============================================================================
__device__ __forceinline__ uint32_t tf32u(float v){
    uint32_t r; asm("cvt.rn.tf32.f32 %0,%1;":"=r"(r):"f"(v)); return r;
}
__device__ __forceinline__ void mma8(float& d0, float& d1, float& d2, float& d3,
                                     uint32_t a0, uint32_t a1, uint32_t a2, uint32_t a3,
                                     uint32_t b0, uint32_t b1){
    asm volatile("mma.sync.aligned.m16n8k8.row.col.f32.tf32.tf32.f32 "
                 "{%0,%1,%2,%3},{%4,%5,%6,%7},{%8,%9},{%0,%1,%2,%3};"
                 : "+f"(d0), "+f"(d1), "+f"(d2), "+f"(d3)
                 : "r"(a0), "r"(a1), "r"(a2), "r"(a3), "r"(b0), "r"(b1));
}

// ============================================================================
// K1: Rodrigues + feature matrix build
// ============================================================================
__global__ void k_pose(const float* __restrict__ pose, const float* __restrict__ shape,
                       const float* __restrict__ expr, const float* __restrict__ go) {
    int b = blockIdx.x, t = threadIdx.x;
    for (int i = t; i < KPAD-KTOT; i += 64) g_F[b*KPAD + KTOT + i] = 0.f;
    if (t < NJ) {
        int j = t;
        float rx, ry, rz;
        if (j == 0)            { rx = go[0]; ry = go[1]; rz = go[2]; }
        else if (j==23||j==24) { rx = 0.f; ry = 0.f; rz = 0.f; }
        else {
            int src = (j <= 21) ? j : (j == 22 ? 52 : j - 3);
            const float* p = pose + (b*53 + src)*3;
            rx = p[0]; ry = p[1]; rz = p[2];
        }
        float ax = rx + 1e-8f, ay = ry + 1e-8f, az = rz + 1e-8f;
        float angle = sqrtf(ax*ax + ay*ay + az*az);
        float inv = 1.f/angle;
        float x = rx*inv, y = ry*inv, z = rz*inv;
        float s = sinf(angle), c = cosf(angle), u = 1.f - c;
        float R[9];
        R[0] = 1.f - u*(y*y+z*z); R[1] = -s*z + u*x*y;      R[2] =  s*y + u*x*z;
        R[3] =  s*z + u*x*y;      R[4] = 1.f - u*(x*x+z*z); R[5] = -s*x + u*y*z;
        R[6] = -s*y + u*x*z;      R[7] =  s*x + u*y*z;      R[8] = 1.f - u*(x*x+y*y);
        float* rm = g_rot + (b*NJ + j)*9;
#pragma unroll
        for (int k = 0; k < 9; k++) rm[k] = R[k];
        if (j >= 1) {
            int kb = KSH + (j-1)*9;
#pragma unroll
            for (int k = 0; k < 9; k++)
                g_F[b*KPAD + kb + k] = R[k] - ((k==0||k==4||k==8) ? 1.f : 0.f);
        }
    }
    for (int i = t; i < KSH; i += 64)
        g_F[b*KPAD + i] = (i < 10) ? shape[b*10 + i] : expr[b*50 + (i-10)];
}

// ============================================================================
// K_sdT: compact+transpose shapedirs' 60 used columns -> g_SDT[k][n]
// reads coalesced (l contiguous per n), writes scattered (amortized once)
// ============================================================================
__global__ void k_sdT(const float* __restrict__ SD) {
    int t = threadIdx.x;                 // 180 threads
    int nl = t / 60, lx = t % 60;
    int n = blockIdx.x*3 + nl;           // NN/3 = 10475 blocks cover all n
    int lsel = (lx < 10) ? lx : lx + 290;
    g_SDT[(size_t)lx*NN + n] = SD[(size_t)n*350 + lsel];
}

// ============================================================================
// K2: JSD partials — coalesced redesign. 64 chunks x 164 v.
// 183 threads each own one output column; 55 joint accumulators in registers.
// ============================================================================
__global__ __launch_bounds__(192) void k_jsdp(const float* __restrict__ Jr,
                                              const float* __restrict__ SD,
                                              const float* __restrict__ vt) {
    int ch = blockIdx.x, t = threadIdx.x;
    int v0 = ch*VT;
    int cnt = min(VT, NV - v0);
    __shared__ float jr_s[NJ][VT];
    for (int j = 0; j < NJ; j++)
        for (int i = t; i < cnt; i += 192) jr_s[j][i] = Jr[(size_t)j*NV + v0 + i];
    __syncthreads();
    if (t >= 183) return;
    bool isvt = (t >= 180);
    int col = 0;
    if (!isvt) {
        int c = t/60, lx = t%60;
        col = c*350 + ((lx < 10) ? lx : lx + 290);
    }
    float acc[NJ];
#pragma unroll
    for (int j = 0; j < NJ; j++) acc[j] = 0.f;
    for (int i = 0; i < cnt; i++) {
        float val = isvt ? vt[(v0+i)*3 + (t-180)]
                         : SD[(size_t)(v0+i)*1050 + col];
#pragma unroll
        for (int j = 0; j < NJ; j++) acc[j] += jr_s[j][i]*val;
    }
#pragma unroll
    for (int j = 0; j < NJ; j++)
        g_JSDp[(size_t)(ch*NJ + j)*184 + t] = acc[j];
}

__global__ void k_jsdf() {
    int j = blockIdx.x, t = threadIdx.x;
    if (t >= 183) return;
    float s = 0.f;
#pragma unroll 8
    for (int ch = 0; ch < NCH; ch++) s += g_JSDp[(size_t)(ch*NJ + j)*184 + t];
    if (t < 180) g_JSD[j*180 + t] = s;
    else         g_Jvt[j*3 + (t-180)] = s;
}

// ============================================================================
// K4: joints
// ============================================================================
__global__ void k_joints() {
    int b = blockIdx.x, t = threadIdx.x;
    __shared__ float fb[KSH];
    for (int i = t; i < KSH; i += 192) fb[i] = g_F[b*KPAD + i];
    __syncthreads();
    if (t < 165) {
        int j = t/3, c = t%3;
        float acc = g_Jvt[j*3 + c];
        const float* jsd = g_JSD + j*180 + c*60;
#pragma unroll
        for (int l = 0; l < KSH; l++) acc += fb[l]*jsd[l];
        g_joints[b*165 + t] = acc;
    }
}

// ============================================================================
// K5: kinematic chain
// ============================================================================
__global__ void k_chain(float* __restrict__ out_joints) {
    int b = blockIdx.x, t = threadIdx.x;
    __shared__ float A[NJ][12];
    __shared__ float jt[NJ][3];
    for (int i = t; i < 165; i += 32) jt[i/3][i%3] = g_joints[b*165 + i];
    __syncwarp();
    if (t < 12) {
        int m = t/4, n = t%4;
        A[0][t] = (n < 3) ? g_rot[(b*NJ)*9 + m*3 + n] : jt[0][m];
    }
    __syncwarp();
    for (int j = 1; j < NJ; j++) {
        if (t < 12) {
            int m = t/4, n = t%4;
            int p = c_parents[j];
            const float* rm = g_rot + (b*NJ + j)*9;
            float acc = (n == 3) ? A[p][m*4+3] : 0.f;
#pragma unroll
            for (int k = 0; k < 3; k++) {
                float tv = (n < 3) ? rm[k*3+n] : (jt[j][k] - jt[p][k]);
                acc += A[p][m*4+k]*tv;
            }
            A[j][t] = acc;
        }
        __syncwarp();
    }
    for (int e = t; e < 660; e += 32) {
        int j = e/12, r = e%12, m = r/4, n = r%4;
        float val = A[j][r];
        if (n == 3) {
            out_joints[b*165 + j*3 + m] = val;
            val -= A[j][m*4+0]*jt[j][0] + A[j][m*4+1]*jt[j][1] + A[j][m*4+2]*jt[j][2];
        }
        g_Arel[b*660 + e] = val;
    }
}

// ============================================================================
// K6: blend GEMM via mma.sync tf32. CTA 128(b) x 128(n), K=576 in 18 chunks.
// B sources: g_SDT (k<60, coalesced) then PD (coalesced).
// ============================================================================
__global__ __launch_bounds__(256) void k_blend_mma(const float* __restrict__ PD,
                                                   const float* __restrict__ vt) {
    __shared__ uint32_t As[32*PITCH];   // [k][m] tf32
    __shared__ uint32_t Bsm[32*PITCH];  // [k][n] tf32
    int tid = threadIdx.x, lane = tid & 31, w = tid >> 5;
    int wm = w >> 2, wn = w & 3;
    int gid = lane >> 2, tig = lane & 3;
    int n0 = blockIdx.x*128, b0 = blockIdx.y*128;

    float acc[4][4][4];
#pragma unroll
    for (int mi = 0; mi < 4; mi++)
#pragma unroll
        for (int ni = 0; ni < 4; ni++)
#pragma unroll
            for (int q = 0; q < 4; q++) acc[mi][ni][q] = 0.f;

    for (int c = 0; c < 18; c++) {
        int k0 = c*32;
        // A fill: float4 LDG from g_F (coalesced), scalar STS (conflict-free)
#pragma unroll
        for (int ii = 0; ii < 4; ii++) {
            int idx = tid + ii*256;          // 0..1023 float4 slots
            int m = idx >> 3, kq = idx & 7;  // 128 m x 8 quads
            float4 v = *(const float4*)&g_F[(b0+m)*KPAD + k0 + kq*4];
            As[(kq*4+0)*PITCH + m] = tf32u(v.x);
            As[(kq*4+1)*PITCH + m] = tf32u(v.y);
            As[(kq*4+2)*PITCH + m] = tf32u(v.z);
            As[(kq*4+3)*PITCH + m] = tf32u(v.w);
        }
        // B fill: scalar LDG, n contiguous -> coalesced for both sources
#pragma unroll
        for (int ii = 0; ii < 16; ii++) {
            int idx = tid + ii*256;          // 0..4095
            int n = idx & 127, k = idx >> 7;
            int kg = k0 + k, ng = n0 + n;
            float v = 0.f;
            if (ng < NN) {
                if (kg < KSH)       v = g_SDT[(size_t)kg*NN + ng];
                else if (kg < KTOT) v = PD[(size_t)(kg-KSH)*NN + ng];
            }
            Bsm[k*PITCH + n] = tf32u(v);
        }
        __syncthreads();
#pragma unroll
        for (int s = 0; s < 4; s++) {
            int ks = s*8;
            uint32_t af[4][4], bf[4][2];
#pragma unroll
            for (int mi = 0; mi < 4; mi++) {
                int row = wm*64 + mi*16 + gid;
                af[mi][0] = As[(ks+tig  )*PITCH + row];
                af[mi][1] = As[(ks+tig  )*PITCH + row + 8];
                af[mi][2] = As[(ks+tig+4)*PITCH + row];
                af[mi][3] = As[(ks+tig+4)*PITCH + row + 8];
            }
#pragma unroll
            for (int ni = 0; ni < 4; ni++) {
                int col = wn*32 + ni*8 + gid;
                bf[ni][0] = Bsm[(ks+tig  )*PITCH + col];
                bf[ni][1] = Bsm[(ks+tig+4)*PITCH + col];
            }
#pragma unroll
            for (int mi = 0; mi < 4; mi++)
#pragma unroll
                for (int ni = 0; ni < 4; ni++)
                    mma8(acc[mi][ni][0], acc[mi][ni][1], acc[mi][ni][2], acc[mi][ni][3],
                         af[mi][0], af[mi][1], af[mi][2], af[mi][3],
                         bf[ni][0], bf[ni][1]);
        }
        __syncthreads();
    }
    // epilogue: add v_template, write v_posed
#pragma unroll
    for (int mi = 0; mi < 4; mi++) {
        int r0 = b0 + wm*64 + mi*16 + gid;
#pragma unroll
        for (int ni = 0; ni < 4; ni++) {
            int cc = wn*32 + ni*8 + 2*tig;
            int n = n0 + cc;
            if (n+1 < NN) {
                g_vposed[(size_t)r0*NN + n]       = acc[mi][ni][0] + vt[n];
                g_vposed[(size_t)r0*NN + n+1]     = acc[mi][ni][1] + vt[n+1];
                g_vposed[(size_t)(r0+8)*NN + n]   = acc[mi][ni][2] + vt[n];
                g_vposed[(size_t)(r0+8)*NN + n+1] = acc[mi][ni][3] + vt[n+1];
            } else if (n < NN) {
                g_vposed[(size_t)r0*NN + n]       = acc[mi][ni][0] + vt[n];
                g_vposed[(size_t)(r0+8)*NN + n]   = acc[mi][ni][2] + vt[n];
            }
        }
    }
}

// ============================================================================
// K7: LBS via mma.sync tf32. CTA: 128 verts x 128 (8 batches x 16 cols), K=64.
// ============================================================================
__global__ __launch_bounds__(256) void k_lbs_mma(const float* __restrict__ W,
                                                 float* __restrict__ verts) {
    extern __shared__ uint32_t sm[];
    uint32_t* As  = sm;               // [64][PITCH]
    uint32_t* Bsm = sm + 64*PITCH;    // [64][PITCH]
    float*    Ds  = (float*)sm;       // [128][132] (reused after MMA)
    int tid = threadIdx.x, lane = tid & 31, w = tid >> 5;
    int wm = w >> 2, wn = w & 3;
    int gid = lane >> 2, tig = lane & 3;
    int vbase = blockIdx.x*128, b0 = blockIdx.y*8;

#pragma unroll
    for (int ii = 0; ii < 32; ii++) {
        int idx = tid + ii*256;
        int j = idx & 63, vl = idx >> 6;
        int v = vbase + vl;
        float val = (j < NJ && v < NV) ? W[(size_t)v*NJ + j] : 0.f;
        As[j*PITCH + vl] = tf32u(val);
    }
#pragma unroll
    for (int ii = 0; ii < 32; ii++) {
        int idx = tid + ii*256;
        int n = idx & 127, j = idx >> 7;
        int bi = n >> 4, q = n & 15;
        float val = (q < 12 && j < NJ) ? g_Arel[(b0+bi)*660 + j*12 + q] : 0.f;
        Bsm[j*PITCH + n] = tf32u(val);
    }
    __syncthreads();

    float acc[4][4][4];
#pragma unroll
    for (int mi = 0; mi < 4; mi++)
#pragma unroll
        for (int ni = 0; ni < 4; ni++)
#pragma unroll
            for (int q = 0; q < 4; q++) acc[mi][ni][q] = 0.f;

#pragma unroll
    for (int s = 0; s < 8; s++) {
        int ks = s*8;
        uint32_t af[4][4], bf[4][2];
#pragma unroll
        for (int mi = 0; mi < 4; mi++) {
            int row = wm*64 + mi*16 + gid;
            af[mi][0] = As[(ks+tig  )*PITCH + row];
            af[mi][1] = As[(ks+tig  )*PITCH + row + 8];
            af[mi][2] = As[(ks+tig+4)*PITCH + row];
            af[mi][3] = As[(ks+tig+4)*PITCH + row + 8];
        }
#pragma unroll
        for (int ni = 0; ni < 4; ni++) {
            int col = wn*32 + ni*8 + gid;
            bf[ni][0] = Bsm[(ks+tig  )*PITCH + col];
            bf[ni][1] = Bsm[(ks+tig+4)*PITCH + col];
        }
#pragma unroll
        for (int mi = 0; mi < 4; mi++)
#pragma unroll
            for (int ni = 0; ni < 4; ni++)
                mma8(acc[mi][ni][0], acc[mi][ni][1], acc[mi][ni][2], acc[mi][ni][3],
                     af[mi][0], af[mi][1], af[mi][2], af[mi][3],
                     bf[ni][0], bf[ni][1]);
    }
    __syncthreads();

#pragma unroll
    for (int mi = 0; mi < 4; mi++) {
        int r = wm*64 + mi*16 + gid;
#pragma unroll
        for (int ni = 0; ni < 4; ni++) {
            int cc = wn*32 + ni*8 + 2*tig;
            *(float2*)&Ds[r*132 + cc]     = make_float2(acc[mi][ni][0], acc[mi][ni][1]);
            *(float2*)&Ds[(r+8)*132 + cc] = make_float2(acc[mi][ni][2], acc[mi][ni][3]);
        }
    }
    __syncthreads();

#pragma unroll
    for (int ii = 0; ii < 4; ii++) {
        int id = tid + ii*256;
        int row = id & 127, bi = id >> 7;
        int v = vbase + row;
        if (v < NV) {
            int b = b0 + bi;
            const float* T = Ds + row*132 + bi*16;
            const float* p = g_vposed + (size_t)b*NN + v*3;
            float p0 = p[0], p1 = p[1], p2 = p[2];
            float* o = verts + (size_t)b*NN + v*3;
#pragma unroll
            for (int m = 0; m < 3; m++)
                o[m] = T[4*m+0]*p0 + T[4*m+1]*p1 + T[4*m+2]*p2 + T[4*m+3];
        }
    }
}

// ============================================================================
extern "C" void kernel_launch(void* const* d_in, const int* in_sizes, int n_in,
                              void* d_out, int out_size) {
    const float* pose  = (const float*)d_in[0];
    const float* shape = (const float*)d_in[1];
    const float* expr  = (const float*)d_in[2];
    const float* go    = (const float*)d_in[3];
    const float* vt    = (const float*)d_in[4];
    const float* SD    = (const float*)d_in[5];
    const float* PD    = (const float*)d_in[6];
    const float* Jr    = (const float*)d_in[7];
    const float* W     = (const float*)d_in[8];
    float* out_verts  = (float*)d_out;
    float* out_joints = (float*)d_out + (size_t)BS*NN;

    int lbs_smem = 2*64*PITCH*4;   // 68096 B (also covers 128*132*4 = 67584)
    cudaFuncSetAttribute(k_lbs_mma, cudaFuncAttributeMaxDynamicSharedMemorySize, lbs_smem);

    // order chosen so k_blend_mma is launch index 3 (ncu slot 5 w/ observed +2 shift)
    k_pose     <<<BS, 64>>>(pose, shape, expr, go);
    k_sdT      <<<NN/3, 180>>>(SD);
    k_jsdp     <<<NCH, 192>>>(Jr, SD, vt);
    k_blend_mma<<<dim3(246, 2), 256>>>(PD, vt);
    k_jsdf     <<<NJ, 192>>>();
    k_joints   <<<BS, 192>>>();
    k_chain    <<<BS, 32>>>(out_joints);
    k_lbs_mma  <<<dim3(82, 32), 256, lbs_smem>>>(W, out_verts);
}

// round 15
// speedup vs baseline: 2.6567x; 2.6567x over previous
#include <cuda_runtime.h>
#include <cstdint>
#include <math.h>

#define BS   256
#define NJ   55
#define NV   10475
#define NN   (NV*3)      // 31425
#define NNP  31488       // padded pitch, = 246*128, divisible by 16
#define KSH  60
#define KTOT 546
#define KPAD 576
#define PITCH 133
#define NCH  64
#define VT   164

// blend pipeline geometry
#define PA   36          // A smem pitch, [m][k] rows of 32 + 4 pad
#define PB   136         // B smem pitch, [k][n] rows of 128 + 8 pad
#define ASZ  (128*PA)    // 4608 floats
#define BSZ  (32*PB)     // 4352 floats
#define STG  (ASZ+BSZ)   // 8960 floats per stage

__constant__ int c_parents[NJ] = {-1,0,0,0,1,2,3,4,5,6,7,8,9,9,9,12,13,14,16,17,18,19,
                                  15,15,15,20,25,26,20,28,29,20,31,32,20,34,35,20,37,38,
                                  21,40,41,21,43,44,21,46,47,21,49,50,21,52,53};

// ---- scratch ----
__device__ float g_F[BS*KPAD];             // feature matrix row-major [b][k], zero-padded
__device__ float g_rot[BS*NJ*9];
__device__ float g_JSDp[NCH*NJ*184];
__device__ float g_JSD[NJ*180];
__device__ float g_Jvt[NJ*3];
__device__ float g_joints[BS*NJ*3];
__device__ float g_Arel[BS*NJ*12];
__device__ float g_BD[(size_t)KTOT*NNP];   // 68.8 MB: [rows 0..59]=SDT, [60..545]=PD, padded
__device__ float g_vposed[BS*NN];          // 32.2 MB

// ============================================================================
// helpers
// ============================================================================
__device__ __forceinline__ uint32_t tf32u(float v){
    uint32_t r; asm("cvt.rn.tf32.f32 %0,%1;":"=r"(r):"f"(v)); return r;
}
__device__ __forceinline__ void mma8(float& d0, float& d1, float& d2, float& d3,
                                     uint32_t a0, uint32_t a1, uint32_t a2, uint32_t a3,
                                     uint32_t b0, uint32_t b1){
    asm volatile("mma.sync.aligned.m16n8k8.row.col.f32.tf32.tf32.f32 "
                 "{%0,%1,%2,%3},{%4,%5,%6,%7},{%8,%9},{%0,%1,%2,%3};"
                 : "+f"(d0), "+f"(d1), "+f"(d2), "+f"(d3)
                 : "r"(a0), "r"(a1), "r"(a2), "r"(a3), "r"(b0), "r"(b1));
}
__device__ __forceinline__ uint32_t sm32(const void* p){
    uint32_t a;
    asm("{ .reg .u64 t; cvta.to.shared.u64 t, %1; cvt.u32.u64 %0, t; }":"=r"(a):"l"(p));
    return a;
}
__device__ __forceinline__ void cp16(uint32_t d, const void* s){
    asm volatile("cp.async.ca.shared.global [%0], [%1], 16;"::"r"(d),"l"(s));
}
__device__ __forceinline__ void cp16z(uint32_t d, const void* s, int bytes){
    asm volatile("cp.async.ca.shared.global [%0], [%1], 16, %2;"::"r"(d),"l"(s),"r"(bytes));
}
#define CPCOMMIT() asm volatile("cp.async.commit_group;":::"memory")
#define CPWAIT1()  asm volatile("cp.async.wait_group 1;":::"memory")
#define CPWAIT0()  asm volatile("cp.async.wait_group 0;":::"memory")

// ============================================================================
// K1: Rodrigues + feature matrix build
// ============================================================================
__global__ void k_pose(const float* __restrict__ pose, const float* __restrict__ shape,
                       const float* __restrict__ expr, const float* __restrict__ go) {
    int b = blockIdx.x, t = threadIdx.x;
    for (int i = t; i < KPAD-KTOT; i += 64) g_F[b*KPAD + KTOT + i] = 0.f;
    if (t < NJ) {
        int j = t;
        float rx, ry, rz;
        if (j == 0)            { rx = go[0]; ry = go[1]; rz = go[2]; }
        else if (j==23||j==24) { rx = 0.f; ry = 0.f; rz = 0.f; }
        else {
            int src = (j <= 21) ? j : (j == 22 ? 52 : j - 3);
            const float* p = pose + (b*53 + src)*3;
            rx = p[0]; ry = p[1]; rz = p[2];
        }
        float ax = rx + 1e-8f, ay = ry + 1e-8f, az = rz + 1e-8f;
        float angle = sqrtf(ax*ax + ay*ay + az*az);
        float inv = 1.f/angle;
        float x = rx*inv, y = ry*inv, z = rz*inv;
        float s = sinf(angle), c = cosf(angle), u = 1.f - c;
        float R[9];
        R[0] = 1.f - u*(y*y+z*z); R[1] = -s*z + u*x*y;      R[2] =  s*y + u*x*z;
        R[3] =  s*z + u*x*y;      R[4] = 1.f - u*(x*x+z*z); R[5] = -s*x + u*y*z;
        R[6] = -s*y + u*x*z;      R[7] =  s*x + u*y*z;      R[8] = 1.f - u*(x*x+y*y);
        float* rm = g_rot + (b*NJ + j)*9;
#pragma unroll
        for (int k = 0; k < 9; k++) rm[k] = R[k];
        if (j >= 1) {
            int kb = KSH + (j-1)*9;
#pragma unroll
            for (int k = 0; k < 9; k++)
                g_F[b*KPAD + kb + k] = R[k] - ((k==0||k==4||k==8) ? 1.f : 0.f);
        }
    }
    for (int i = t; i < KSH; i += 64)
        g_F[b*KPAD + i] = (i < 10) ? shape[b*10 + i] : expr[b*50 + (i-10)];
}

// ============================================================================
// K_sdT: compact+transpose shapedirs' 60 used cols -> g_BD rows [0,60)
// coalesced read (l contiguous per n), scattered write (once)
// ============================================================================
__global__ void k_sdT(const float* __restrict__ SD) {
    int t = threadIdx.x;                 // 180 threads
    int nl = t / 60, lx = t % 60;
    int n = blockIdx.x*3 + nl;
    int lsel = (lx < 10) ? lx : lx + 290;
    g_BD[(size_t)lx*NNP + n] = SD[(size_t)n*350 + lsel];
}

// K_pdcp: copy PD into g_BD rows [60,546) (coalesced) + zero all pad columns
__global__ void k_pdcp(const float* __restrict__ PD) {
    int row = blockIdx.x;                // 0..545
    int n = blockIdx.y*256 + threadIdx.x;
    if (n >= NNP) return;
    if (n >= NN)       g_BD[(size_t)row*NNP + n] = 0.f;
    else if (row >= KSH) g_BD[(size_t)row*NNP + n] = PD[(size_t)(row-KSH)*NN + n];
}

// ============================================================================
// K2: JSD partials — coalesced. 64 chunks x 164 v.
// ============================================================================
__global__ __launch_bounds__(192) void k_jsdp(const float* __restrict__ Jr,
                                              const float* __restrict__ SD,
                                              const float* __restrict__ vt) {
    int ch = blockIdx.x, t = threadIdx.x;
    int v0 = ch*VT;
    int cnt = min(VT, NV - v0);
    __shared__ float jr_s[NJ][VT];
    for (int j = 0; j < NJ; j++)
        for (int i = t; i < cnt; i += 192) jr_s[j][i] = Jr[(size_t)j*NV + v0 + i];
    __syncthreads();
    if (t >= 183) return;
    bool isvt = (t >= 180);
    int col = 0;
    if (!isvt) {
        int c = t/60, lx = t%60;
        col = c*350 + ((lx < 10) ? lx : lx + 290);
    }
    float acc[NJ];
#pragma unroll
    for (int j = 0; j < NJ; j++) acc[j] = 0.f;
    for (int i = 0; i < cnt; i++) {
        float val = isvt ? vt[(v0+i)*3 + (t-180)]
                         : SD[(size_t)(v0+i)*1050 + col];
#pragma unroll
        for (int j = 0; j < NJ; j++) acc[j] += jr_s[j][i]*val;
    }
#pragma unroll
    for (int j = 0; j < NJ; j++)
        g_JSDp[(size_t)(ch*NJ + j)*184 + t] = acc[j];
}

__global__ void k_jsdf() {
    int j = blockIdx.x, t = threadIdx.x;
    if (t >= 183) return;
    float s = 0.f;
#pragma unroll 8
    for (int ch = 0; ch < NCH; ch++) s += g_JSDp[(size_t)(ch*NJ + j)*184 + t];
    if (t < 180) g_JSD[j*180 + t] = s;
    else         g_Jvt[j*3 + (t-180)] = s;
}

// ============================================================================
// K4: joints
// ============================================================================
__global__ void k_joints() {
    int b = blockIdx.x, t = threadIdx.x;
    __shared__ float fb[KSH];
    for (int i = t; i < KSH; i += 192) fb[i] = g_F[b*KPAD + i];
    __syncthreads();
    if (t < 165) {
        int j = t/3, c = t%3;
        float acc = g_Jvt[j*3 + c];
        const float* jsd = g_JSD + j*180 + c*60;
#pragma unroll
        for (int l = 0; l < KSH; l++) acc += fb[l]*jsd[l];
        g_joints[b*165 + t] = acc;
    }
}

// ============================================================================
// K5: kinematic chain
// ============================================================================
__global__ void k_chain(float* __restrict__ out_joints) {
    int b = blockIdx.x, t = threadIdx.x;
    __shared__ float A[NJ][12];
    __shared__ float jt[NJ][3];
    for (int i = t; i < 165; i += 32) jt[i/3][i%3] = g_joints[b*165 + i];
    __syncwarp();
    if (t < 12) {
        int m = t/4, n = t%4;
        A[0][t] = (n < 3) ? g_rot[(b*NJ)*9 + m*3 + n] : jt[0][m];
    }
    __syncwarp();
    for (int j = 1; j < NJ; j++) {
        if (t < 12) {
            int m = t/4, n = t%4;
            int p = c_parents[j];
            const float* rm = g_rot + (b*NJ + j)*9;
            float acc = (n == 3) ? A[p][m*4+3] : 0.f;
#pragma unroll
            for (int k = 0; k < 3; k++) {
                float tv = (n < 3) ? rm[k*3+n] : (jt[j][k] - jt[p][k]);
                acc += A[p][m*4+k]*tv;
            }
            A[j][t] = acc;
        }
        __syncwarp();
    }
    for (int e = t; e < 660; e += 32) {
        int j = e/12, r = e%12, m = r/4, n = r%4;
        float val = A[j][r];
        if (n == 3) {
            out_joints[b*165 + j*3 + m] = val;
            val -= A[j][m*4+0]*jt[j][0] + A[j][m*4+1]*jt[j][1] + A[j][m*4+2]*jt[j][2];
        }
        g_Arel[b*660 + e] = val;
    }
}

// ============================================================================
// K6: blend GEMM — cp.async double-buffered, 2 CTA/SM, tf32 MMA (raw bits).
// CTA 128(b) x 128(n), K=576 in 18 chunks of 32. All cp.async srcs 16B-aligned.
// ============================================================================
__device__ __forceinline__ void blend_issue(float* stage, int tid, int b0, int n0, int c) {
    float* As  = stage;
    float* Bs2 = stage + ASZ;
    int k0 = c*32;
#pragma unroll
    for (int ii = 0; ii < 4; ii++) {
        int t4 = tid + ii*256;           // 0..1023
        int m = t4 >> 3, q = t4 & 7;
        cp16(sm32(As + m*PA + q*4), &g_F[(b0+m)*KPAD + k0 + q*4]);
    }
#pragma unroll
    for (int ii = 0; ii < 4; ii++) {
        int t4 = tid + ii*256;           // 0..1023
        int k = t4 >> 5, nq = t4 & 31;
        int kg = k0 + k;
        int bytes = (kg < KTOT) ? 16 : 0;
        cp16z(sm32(Bs2 + k*PB + nq*4),
              &g_BD[(size_t)kg*NNP + n0 + nq*4], bytes);
    }
}

__global__ __launch_bounds__(256,2) void k_blend_pipe(const float* __restrict__ vt) {
    extern __shared__ float smf[];
    int tid = threadIdx.x, lane = tid & 31, w = tid >> 5;
    int wm = w >> 2, wn = w & 3;
    int gid = lane >> 2, tig = lane & 3;
    int n0 = blockIdx.x*128, b0 = blockIdx.y*128;

    float acc[4][4][4];
#pragma unroll
    for (int mi = 0; mi < 4; mi++)
#pragma unroll
        for (int ni = 0; ni < 4; ni++)
#pragma unroll
            for (int q = 0; q < 4; q++) acc[mi][ni][q] = 0.f;

    blend_issue(smf, tid, b0, n0, 0);
    CPCOMMIT();

    for (int c = 0; c < 18; c++) {
        int s = c & 1;
        if (c < 17) {
            blend_issue(smf + (s^1)*STG, tid, b0, n0, c+1);
            CPCOMMIT();
            CPWAIT1();
        } else {
            CPWAIT0();
        }
        __syncthreads();
        const uint32_t* Au = (const uint32_t*)(smf + s*STG);
        const uint32_t* Bu = Au + ASZ;
#pragma unroll
        for (int st = 0; st < 4; st++) {
            int ks = st*8;
            uint32_t af[4][4], bf[4][2];
#pragma unroll
            for (int mi = 0; mi < 4; mi++) {
                int row = wm*64 + mi*16 + gid;
                af[mi][0] = Au[row*PA     + ks+tig];
                af[mi][1] = Au[(row+8)*PA + ks+tig];
                af[mi][2] = Au[row*PA     + ks+tig+4];
                af[mi][3] = Au[(row+8)*PA + ks+tig+4];
            }
#pragma unroll
            for (int ni = 0; ni < 4; ni++) {
                int col = wn*32 + ni*8 + gid;
                bf[ni][0] = Bu[(ks+tig  )*PB + col];
                bf[ni][1] = Bu[(ks+tig+4)*PB + col];
            }
#pragma unroll
            for (int mi = 0; mi < 4; mi++)
#pragma unroll
                for (int ni = 0; ni < 4; ni++)
                    mma8(acc[mi][ni][0], acc[mi][ni][1], acc[mi][ni][2], acc[mi][ni][3],
                         af[mi][0], af[mi][1], af[mi][2], af[mi][3],
                         bf[ni][0], bf[ni][1]);
        }
        __syncthreads();   // stage s reusable for chunk c+2
    }

    // epilogue: add v_template, write v_posed
#pragma unroll
    for (int mi = 0; mi < 4; mi++) {
        int r0 = b0 + wm*64 + mi*16 + gid;
#pragma unroll
        for (int ni = 0; ni < 4; ni++) {
            int cc = wn*32 + ni*8 + 2*tig;
            int n = n0 + cc;
            if (n+1 < NN) {
                g_vposed[(size_t)r0*NN + n]       = acc[mi][ni][0] + vt[n];
                g_vposed[(size_t)r0*NN + n+1]     = acc[mi][ni][1] + vt[n+1];
                g_vposed[(size_t)(r0+8)*NN + n]   = acc[mi][ni][2] + vt[n];
                g_vposed[(size_t)(r0+8)*NN + n+1] = acc[mi][ni][3] + vt[n+1];
            } else if (n < NN) {
                g_vposed[(size_t)r0*NN + n]       = acc[mi][ni][0] + vt[n];
                g_vposed[(size_t)(r0+8)*NN + n]   = acc[mi][ni][2] + vt[n];
            }
        }
    }
}

// ============================================================================
// K7: LBS via mma.sync tf32. CTA: 128 verts x 128 (8 batches x 16 cols), K=64.
// ============================================================================
__global__ __launch_bounds__(256,2) void k_lbs_mma(const float* __restrict__ W,
                                                   float* __restrict__ verts) {
    extern __shared__ uint32_t sm[];
    uint32_t* As  = sm;               // [64][PITCH]
    uint32_t* Bsm = sm + 64*PITCH;    // [64][PITCH]
    float*    Ds  = (float*)sm;       // [128][132] (reused after MMA)
    int tid = threadIdx.x, lane = tid & 31, w = tid >> 5;
    int wm = w >> 2, wn = w & 3;
    int gid = lane >> 2, tig = lane & 3;
    int vbase = blockIdx.x*128, b0 = blockIdx.y*8;

#pragma unroll
    for (int ii = 0; ii < 32; ii++) {
        int idx = tid + ii*256;
        int j = idx & 63, vl = idx >> 6;
        int v = vbase + vl;
        float val = (j < NJ && v < NV) ? W[(size_t)v*NJ + j] : 0.f;
        As[j*PITCH + vl] = tf32u(val);
    }
#pragma unroll
    for (int ii = 0; ii < 32; ii++) {
        int idx = tid + ii*256;
        int n = idx & 127, j = idx >> 7;
        int bi = n >> 4, q = n & 15;
        float val = (q < 12 && j < NJ) ? g_Arel[(b0+bi)*660 + j*12 + q] : 0.f;
        Bsm[j*PITCH + n] = tf32u(val);
    }
    __syncthreads();

    float acc[4][4][4];
#pragma unroll
    for (int mi = 0; mi < 4; mi++)
#pragma unroll
        for (int ni = 0; ni < 4; ni++)
#pragma unroll
            for (int q = 0; q < 4; q++) acc[mi][ni][q] = 0.f;

#pragma unroll
    for (int s = 0; s < 8; s++) {
        int ks = s*8;
        uint32_t af[4][4], bf[4][2];
#pragma unroll
        for (int mi = 0; mi < 4; mi++) {
            int row = wm*64 + mi*16 + gid;
            af[mi][0] = As[(ks+tig  )*PITCH + row];
            af[mi][1] = As[(ks+tig  )*PITCH + row + 8];
            af[mi][2] = As[(ks+tig+4)*PITCH + row];
            af[mi][3] = As[(ks+tig+4)*PITCH + row + 8];
        }
#pragma unroll
        for (int ni = 0; ni < 4; ni++) {
            int col = wn*32 + ni*8 + gid;
            bf[ni][0] = Bsm[(ks+tig  )*PITCH + col];
            bf[ni][1] = Bsm[(ks+tig+4)*PITCH + col];
        }
#pragma unroll
        for (int mi = 0; mi < 4; mi++)
#pragma unroll
            for (int ni = 0; ni < 4; ni++)
                mma8(acc[mi][ni][0], acc[mi][ni][1], acc[mi][ni][2], acc[mi][ni][3],
                     af[mi][0], af[mi][1], af[mi][2], af[mi][3],
                     bf[ni][0], bf[ni][1]);
    }
    __syncthreads();

#pragma unroll
    for (int mi = 0; mi < 4; mi++) {
        int r = wm*64 + mi*16 + gid;
#pragma unroll
        for (int ni = 0; ni < 4; ni++) {
            int cc = wn*32 + ni*8 + 2*tig;
            *(float2*)&Ds[r*132 + cc]     = make_float2(acc[mi][ni][0], acc[mi][ni][1]);
            *(float2*)&Ds[(r+8)*132 + cc] = make_float2(acc[mi][ni][2], acc[mi][ni][3]);
        }
    }
    __syncthreads();

#pragma unroll
    for (int ii = 0; ii < 4; ii++) {
        int id = tid + ii*256;
        int row = id & 127, bi = id >> 7;
        int v = vbase + row;
        if (v < NV) {
            int b = b0 + bi;
            const float* T = Ds + row*132 + bi*16;
            const float* p = g_vposed + (size_t)b*NN + v*3;
            float p0 = p[0], p1 = p[1], p2 = p[2];
            float* o = verts + (size_t)b*NN + v*3;
#pragma unroll
            for (int m = 0; m < 3; m++)
                o[m] = T[4*m+0]*p0 + T[4*m+1]*p1 + T[4*m+2]*p2 + T[4*m+3];
        }
    }
}

// ============================================================================
extern "C" void kernel_launch(void* const* d_in, const int* in_sizes, int n_in,
                              void* d_out, int out_size) {
    const float* pose  = (const float*)d_in[0];
    const float* shape = (const float*)d_in[1];
    const float* expr  = (const float*)d_in[2];
    const float* go    = (const float*)d_in[3];
    const float* vt    = (const float*)d_in[4];
    const float* SD    = (const float*)d_in[5];
    const float* PD    = (const float*)d_in[6];
    const float* Jr    = (const float*)d_in[7];
    const float* W     = (const float*)d_in[8];
    float* out_verts  = (float*)d_out;
    float* out_joints = (float*)d_out + (size_t)BS*NN;

    int blend_smem = 2*STG*4;      // 71680 B
    int lbs_smem   = 2*64*PITCH*4; // 68096 B
    cudaFuncSetAttribute(k_blend_pipe, cudaFuncAttributeMaxDynamicSharedMemorySize, blend_smem);
    cudaFuncSetAttribute(k_lbs_mma,    cudaFuncAttributeMaxDynamicSharedMemorySize, lbs_smem);

    k_pose      <<<BS, 64>>>(pose, shape, expr, go);
    k_sdT       <<<NV, 180>>>(SD);
    k_pdcp      <<<dim3(KTOT, (NNP+255)/256), 256>>>(PD);
    k_blend_pipe<<<dim3(246, 2), 256, blend_smem>>>(vt);
    k_jsdp      <<<NCH, 192>>>(Jr, SD, vt);
    k_jsdf      <<<NJ, 192>>>();
    k_joints    <<<BS, 192>>>();
    k_chain     <<<BS, 32>>>(out_joints);
    k_lbs_mma   <<<dim3(82, 32), 256, lbs_smem>>>(W, out_verts);
}